// round 1
// baseline (speedup 1.0000x reference)
#include <cuda_runtime.h>

#define N1 60000
#define N2 50000
#define EDGES 800000
#define DIMV 128
#define NR 16
#define LCN 100
#define KTOT 640

// ------------------------- scratch (device globals) -------------------------
__device__ float g_xg1[N1 * DIMV];          // concept-layer output (relu'd)
__device__ float g_A[N2 * KTOT];            // [x | agg4] GEMM input (50000 x 640)
__device__ float g_xa[N2 * DIMV];           // rgcn1 output (relu'd)
__device__ float g_xb[N2 * DIMV];           // rgcn2 output
__device__ float g_W1[KTOT * DIMV];         // [root1; basis1_flat]
__device__ float g_W2[KTOT * DIMV];         // [root2; basis2_flat]
__device__ float g_tywT[DIMV * LCN];        // (ty * w)^T  [d][l]
__device__ int g_hist1[N1];
__device__ int g_rp1[N1 + 1];
__device__ int g_cur1[N1];
__device__ int g_col1[EDGES];
__device__ int g_hist2[N2];
__device__ int g_rp2[N2 + 1];
__device__ int g_cur2[N2];
__device__ int g_col2[EDGES];               // packed: src | (etype<<16)
__device__ int g_cseg[N2 * NR];

// ------------------------------- kernels ------------------------------------

__global__ void zero_kernel() {
    int i = blockIdx.x * blockDim.x + threadIdx.x;
    if (i < N1) g_hist1[i] = 0;
    if (i < N2) g_hist2[i] = 0;
    if (i < N2 * NR) g_cseg[i] = 0;
}

__global__ void hist_kernel(const int* __restrict__ ei1,
                            const int* __restrict__ ei2,
                            const int* __restrict__ et2) {
    int i = blockIdx.x * blockDim.x + threadIdx.x;
    if (i >= EDGES) return;
    int d1 = ei1[EDGES + i];
    atomicAdd(&g_hist1[d1], 1);
    int d2 = ei2[EDGES + i];
    atomicAdd(&g_hist2[d2], 1);
    int t = et2[i];
    atomicAdd(&g_cseg[d2 * NR + t], 1);
}

// single-block exclusive scan per graph (blockIdx.x selects graph)
__global__ void scan_kernel() {
    int which = blockIdx.x;
    int n = which ? N2 : N1;
    int* hist = which ? g_hist2 : g_hist1;
    int* rp   = which ? g_rp2   : g_rp1;
    int* cur  = which ? g_cur2  : g_cur1;

    __shared__ int wsum[32];
    __shared__ int carry_s;
    int tid = threadIdx.x, lane = tid & 31, wid = tid >> 5;
    if (tid == 0) carry_s = 0;
    __syncthreads();

    for (int base = 0; base < n; base += 1024) {
        int i = base + tid;
        int v = (i < n) ? hist[i] : 0;
        int incl = v;
        #pragma unroll
        for (int off = 1; off < 32; off <<= 1) {
            int t = __shfl_up_sync(0xFFFFFFFFu, incl, off);
            if (lane >= off) incl += t;
        }
        if (lane == 31) wsum[wid] = incl;
        __syncthreads();
        if (wid == 0) {
            int s = wsum[lane];
            #pragma unroll
            for (int off = 1; off < 32; off <<= 1) {
                int t = __shfl_up_sync(0xFFFFFFFFu, s, off);
                if (lane >= off) s += t;
            }
            wsum[lane] = s;
        }
        __syncthreads();
        int woff = wid ? wsum[wid - 1] : 0;
        int excl = carry_s + woff + incl - v;
        if (i < n) { rp[i] = excl; cur[i] = excl; }
        __syncthreads();
        if (tid == 1023) carry_s += woff + incl;   // total of this chunk
        __syncthreads();
    }
    if (threadIdx.x == 0) rp[n] = carry_s;
}

__global__ void scatter_kernel(const int* __restrict__ ei1,
                               const int* __restrict__ ei2,
                               const int* __restrict__ et2) {
    int i = blockIdx.x * blockDim.x + threadIdx.x;
    if (i >= EDGES) return;
    int s1 = ei1[i], d1 = ei1[EDGES + i];
    int p1 = atomicAdd(&g_cur1[d1], 1);
    g_col1[p1] = s1;
    int s2 = ei2[i], d2 = ei2[EDGES + i], t = et2[i];
    int p2 = atomicAdd(&g_cur2[d2], 1);
    g_col2[p2] = s2 | (t << 16);
}

// concept layer: warp per node; relu(x + mean of neighbors)
__global__ void concept_kernel(const float4* __restrict__ x) {
    int gw = (blockIdx.x * blockDim.x + threadIdx.x) >> 5;
    if (gw >= N1) return;
    int lane = threadIdx.x & 31;
    int b = g_rp1[gw], e = g_rp1[gw + 1];
    float4 acc = make_float4(0.f, 0.f, 0.f, 0.f);
    for (int j = b; j < e; j++) {
        int s = g_col1[j];
        float4 xs = x[s * 32 + lane];
        acc.x += xs.x; acc.y += xs.y; acc.z += xs.z; acc.w += xs.w;
    }
    float inv = 1.f / (float)max(e - b, 1);
    float4 xv = x[gw * 32 + lane];
    float4 r;
    r.x = fmaxf(fmaf(acc.x, inv, xv.x), 0.f);
    r.y = fmaxf(fmaf(acc.y, inv, xv.y), 0.f);
    r.z = fmaxf(fmaf(acc.z, inv, xv.z), 0.f);
    r.w = fmaxf(fmaf(acc.w, inv, xv.w), 0.f);
    ((float4*)g_xg1)[gw * 32 + lane] = r;
}

__global__ void wbuild_kernel(const float* __restrict__ root1, const float* __restrict__ b1,
                              const float* __restrict__ root2, const float* __restrict__ b2) {
    int i = blockIdx.x * blockDim.x + threadIdx.x;
    if (i < 128 * 128) { g_W1[i] = root1[i]; g_W2[i] = root2[i]; }
    if (i < 512 * 128) { g_W1[128 * 128 + i] = b1[i]; g_W2[128 * 128 + i] = b2[i]; }
}

// RGCN aggregation: warp per dst node; builds A row = [x_dst | agg_b0..b3]
__global__ void agg_kernel(int layer, const float* __restrict__ comp) {
    __shared__ float4 comps[NR];
    int tid = threadIdx.x;
    if (tid < NR)
        comps[tid] = make_float4(comp[tid * 4 + 0], comp[tid * 4 + 1],
                                 comp[tid * 4 + 2], comp[tid * 4 + 3]);
    __syncthreads();
    int gw = (blockIdx.x * blockDim.x + tid) >> 5;
    if (gw >= N2) return;
    int lane = tid & 31;
    const float4* x = layer ? (const float4*)g_xa : (const float4*)g_xg1;

    float nrm = 0.f;
    if (lane < NR) {
        int c = g_cseg[gw * NR + lane];
        nrm = 1.f / (float)max(c, 1);
    }
    int b = g_rp2[gw], e = g_rp2[gw + 1];
    float4 a0 = make_float4(0.f, 0.f, 0.f, 0.f);
    float4 a1 = a0, a2 = a0, a3 = a0;
    for (int j = b; j < e; j++) {
        int pk = g_col2[j];
        int s = pk & 0xFFFF;
        int et = pk >> 16;
        float nz = __shfl_sync(0xFFFFFFFFu, nrm, et);
        float4 c4 = comps[et];
        float4 xs = x[s * 32 + lane];
        float c0 = c4.x * nz, c1 = c4.y * nz, c2 = c4.z * nz, c3 = c4.w * nz;
        a0.x = fmaf(c0, xs.x, a0.x); a0.y = fmaf(c0, xs.y, a0.y);
        a0.z = fmaf(c0, xs.z, a0.z); a0.w = fmaf(c0, xs.w, a0.w);
        a1.x = fmaf(c1, xs.x, a1.x); a1.y = fmaf(c1, xs.y, a1.y);
        a1.z = fmaf(c1, xs.z, a1.z); a1.w = fmaf(c1, xs.w, a1.w);
        a2.x = fmaf(c2, xs.x, a2.x); a2.y = fmaf(c2, xs.y, a2.y);
        a2.z = fmaf(c2, xs.z, a2.z); a2.w = fmaf(c2, xs.w, a2.w);
        a3.x = fmaf(c3, xs.x, a3.x); a3.y = fmaf(c3, xs.y, a3.y);
        a3.z = fmaf(c3, xs.z, a3.z); a3.w = fmaf(c3, xs.w, a3.w);
    }
    float4* Arow = (float4*)(g_A + (size_t)gw * KTOT);
    Arow[lane]       = x[gw * 32 + lane];
    Arow[32 + lane]  = a0;
    Arow[64 + lane]  = a1;
    Arow[96 + lane]  = a2;
    Arow[128 + lane] = a3;
}

// C[M x 128] = A[M x 640] @ W[640 x 128] + bias  (optional relu)
__global__ __launch_bounds__(256) void gemm_kernel(int layer, const float* __restrict__ bias,
                                                   int relu) {
    __shared__ float As[16][132];
    __shared__ float Ws[16][132];
    const float* A = g_A;
    const float* W = layer ? g_W2 : g_W1;
    float* C = layer ? g_xb : g_xa;
    const int M = N2;

    const int tid = threadIdx.x;
    const int m0 = blockIdx.x * 128;
    const int ar = tid >> 2;           // 0..63
    const int ac = (tid & 3) * 4;      // 0,4,8,12
    const int wr = tid >> 5;           // 0..7
    const int wc = (tid & 31) * 4;     // 0..124
    const int tm = (tid >> 4) * 8;
    const int tn = (tid & 15) * 8;

    float acc[8][8];
    #pragma unroll
    for (int i = 0; i < 8; i++)
        #pragma unroll
        for (int j = 0; j < 8; j++) acc[i][j] = 0.f;

    for (int k0 = 0; k0 < KTOT; k0 += 16) {
        #pragma unroll
        for (int h = 0; h < 2; h++) {
            int m = m0 + ar + h * 64;
            float4 v = make_float4(0.f, 0.f, 0.f, 0.f);
            if (m < M) v = *(const float4*)(A + (size_t)m * KTOT + k0 + ac);
            As[ac + 0][ar + h * 64] = v.x;
            As[ac + 1][ar + h * 64] = v.y;
            As[ac + 2][ar + h * 64] = v.z;
            As[ac + 3][ar + h * 64] = v.w;
        }
        #pragma unroll
        for (int h = 0; h < 2; h++) {
            float4 v = *(const float4*)(W + (k0 + wr + h * 8) * DIMV + wc);
            *(float4*)&Ws[wr + h * 8][wc] = v;
        }
        __syncthreads();
        #pragma unroll
        for (int kk = 0; kk < 16; kk++) {
            float a[8], b[8];
            *(float4*)&a[0] = *(const float4*)&As[kk][tm];
            *(float4*)&a[4] = *(const float4*)&As[kk][tm + 4];
            *(float4*)&b[0] = *(const float4*)&Ws[kk][tn];
            *(float4*)&b[4] = *(const float4*)&Ws[kk][tn + 4];
            #pragma unroll
            for (int i = 0; i < 8; i++)
                #pragma unroll
                for (int j = 0; j < 8; j++)
                    acc[i][j] = fmaf(a[i], b[j], acc[i][j]);
        }
        __syncthreads();
    }
    #pragma unroll
    for (int i = 0; i < 8; i++) {
        int m = m0 + tm + i;
        if (m >= M) break;
        #pragma unroll
        for (int j = 0; j < 8; j += 4) {
            float4 o;
            o.x = acc[i][j + 0] + bias[tn + j + 0];
            o.y = acc[i][j + 1] + bias[tn + j + 1];
            o.z = acc[i][j + 2] + bias[tn + j + 2];
            o.w = acc[i][j + 3] + bias[tn + j + 3];
            if (relu) {
                o.x = fmaxf(o.x, 0.f); o.y = fmaxf(o.y, 0.f);
                o.z = fmaxf(o.z, 0.f); o.w = fmaxf(o.w, 0.f);
            }
            *(float4*)(C + (size_t)m * DIMV + tn + j) = o;
        }
    }
}

__global__ void tyw_kernel(const int* __restrict__ lc, const float* __restrict__ w) {
    int i = blockIdx.x * blockDim.x + threadIdx.x;
    if (i >= DIMV * LCN) return;
    int d = i / LCN, l = i % LCN;
    g_tywT[i] = g_xg1[(size_t)lc[l] * DIMV + d] * w[d];
}

// logits + softmax: warp per row, tyw^T in dynamic smem
__global__ void logits_kernel(float* __restrict__ out) {
    extern __shared__ float sh[];
    float* tw = sh;                    // 12800 floats [d][l]
    float* xr = sh + DIMV * LCN;       // 8 warps * 128
    int tid = threadIdx.x;
    for (int i = tid; i < DIMV * LCN; i += blockDim.x) tw[i] = g_tywT[i];
    __syncthreads();
    int lane = tid & 31, wid = tid >> 5;
    const float4* xg2 = (const float4*)g_xb;

    for (int row = blockIdx.x * 8 + wid; row < N2; row += gridDim.x * 8) {
        float4 xv = xg2[row * 32 + lane];
        *(float4*)&xr[wid * 128 + lane * 4] = xv;
        __syncwarp();
        float d0 = 0.f, d1 = 0.f, d2 = 0.f, d3 = 0.f;
        #pragma unroll 4
        for (int d = 0; d < DIMV; d++) {
            float xd = xr[wid * 128 + d];
            d0 = fmaf(xd, tw[d * LCN + lane], d0);
            d1 = fmaf(xd, tw[d * LCN + lane + 32], d1);
            d2 = fmaf(xd, tw[d * LCN + lane + 64], d2);
            float t3 = (lane < 4) ? tw[d * LCN + lane + 96] : 0.f;
            d3 = fmaf(xd, t3, d3);
        }
        float d3m = (lane < 4) ? d3 : -1e30f;
        float mx = fmaxf(fmaxf(d0, d1), fmaxf(d2, d3m));
        #pragma unroll
        for (int off = 16; off > 0; off >>= 1)
            mx = fmaxf(mx, __shfl_xor_sync(0xFFFFFFFFu, mx, off));
        float e0 = expf(d0 - mx), e1 = expf(d1 - mx), e2 = expf(d2 - mx);
        float e3 = (lane < 4) ? expf(d3 - mx) : 0.f;
        float s = e0 + e1 + e2 + e3;
        #pragma unroll
        for (int off = 16; off > 0; off >>= 1)
            s += __shfl_xor_sync(0xFFFFFFFFu, s, off);
        float inv = 1.f / s;
        float* orow = out + (size_t)row * LCN;
        orow[lane] = e0 * inv;
        orow[lane + 32] = e1 * inv;
        orow[lane + 64] = e2 * inv;
        if (lane < 4) orow[lane + 96] = e3 * inv;
        __syncwarp();
    }
}

// ------------------------------- launcher -----------------------------------
extern "C" void kernel_launch(void* const* d_in, const int* in_sizes, int n_in,
                              void* d_out, int out_size) {
    const int* ei2 = (const int*)d_in[0];
    const int* et2 = (const int*)d_in[1];
    const int* ei1 = (const int*)d_in[2];
    const int* lc  = (const int*)d_in[3];
    const float* x0     = (const float*)d_in[4];
    const float* basis1 = (const float*)d_in[5];
    const float* comp1  = (const float*)d_in[6];
    const float* root1  = (const float*)d_in[7];
    const float* bias1  = (const float*)d_in[8];
    const float* basis2 = (const float*)d_in[9];
    const float* comp2  = (const float*)d_in[10];
    const float* root2  = (const float*)d_in[11];
    const float* bias2  = (const float*)d_in[12];
    const float* w      = (const float*)d_in[13];
    float* out = (float*)d_out;

    zero_kernel<<<(N2 * NR + 255) / 256, 256>>>();
    hist_kernel<<<(EDGES + 255) / 256, 256>>>(ei1, ei2, et2);
    scan_kernel<<<2, 1024>>>();
    scatter_kernel<<<(EDGES + 255) / 256, 256>>>(ei1, ei2, et2);
    concept_kernel<<<N1 / 8, 256>>>((const float4*)x0);
    wbuild_kernel<<<(512 * 128 + 255) / 256, 256>>>(root1, basis1, root2, basis2);

    agg_kernel<<<N2 / 8, 256>>>(0, comp1);
    gemm_kernel<<<(N2 + 127) / 128, 256>>>(0, bias1, 1);
    agg_kernel<<<N2 / 8, 256>>>(1, comp2);
    gemm_kernel<<<(N2 + 127) / 128, 256>>>(1, bias2, 0);

    tyw_kernel<<<(DIMV * LCN + 255) / 256, 256>>>(lc, w);

    static const int LOGITS_SMEM = (DIMV * LCN + 8 * 128) * sizeof(float);  // 55296 B
    cudaFuncSetAttribute(logits_kernel, cudaFuncAttributeMaxDynamicSharedMemorySize,
                         LOGITS_SMEM);
    logits_kernel<<<296, 256, LOGITS_SMEM>>>(out);
}

// round 3
// speedup vs baseline: 1.6226x; 1.6226x over previous
#include <cuda_runtime.h>
#include <cuda_bf16.h>
#include <cstdint>

#define N1 60000
#define N2 50000
#define EDGES 800000
#define DIMV 128
#define NR 16
#define LCN 100
#define KTOT 640

// ------------------------- scratch (device globals) -------------------------
__device__ float g_xg1[N1 * DIMV];                 // concept-layer output (relu'd)
__device__ __nv_bfloat16 g_Ah[N2 * KTOT];          // [x | agg4] hi (bf16)
__device__ __nv_bfloat16 g_Al[N2 * KTOT];          // [x | agg4] lo (bf16)
__device__ float g_xa[N2 * DIMV];                  // rgcn1 output (relu'd)
__device__ float g_xb[N2 * DIMV];                  // rgcn2 output
__device__ __nv_bfloat16 g_Wh[2 * DIMV * KTOT];    // Wt[n][k] hi, both layers
__device__ __nv_bfloat16 g_Wl[2 * DIMV * KTOT];    // Wt[n][k] lo
__device__ float g_tywT[DIMV * LCN];               // (ty * w)^T  [d][l]
__device__ int g_hist1[N1];
__device__ int g_rp1[N1 + 1];
__device__ int g_cur1[N1];
__device__ int g_col1[EDGES];
__device__ int g_hist2[N2];
__device__ int g_rp2[N2 + 1];
__device__ int g_cur2[N2];
__device__ int g_col2[EDGES];                      // packed: src | (etype<<16)
__device__ int g_cseg[N2 * NR];

// ------------------------------- CSR build ----------------------------------
__global__ void zero_kernel() {
    int i = blockIdx.x * blockDim.x + threadIdx.x;
    if (i < N1) g_hist1[i] = 0;
    if (i < N2) g_hist2[i] = 0;
    if (i < N2 * NR) g_cseg[i] = 0;
}

__global__ void hist_kernel(const int* __restrict__ ei1,
                            const int* __restrict__ ei2,
                            const int* __restrict__ et2) {
    int i = blockIdx.x * blockDim.x + threadIdx.x;
    if (i >= EDGES) return;
    atomicAdd(&g_hist1[ei1[EDGES + i]], 1);
    int d2 = ei2[EDGES + i];
    atomicAdd(&g_hist2[d2], 1);
    atomicAdd(&g_cseg[d2 * NR + et2[i]], 1);
}

__global__ void scan_kernel() {
    int which = blockIdx.x;
    int n = which ? N2 : N1;
    int* hist = which ? g_hist2 : g_hist1;
    int* rp   = which ? g_rp2   : g_rp1;
    int* cur  = which ? g_cur2  : g_cur1;

    __shared__ int wsum[32];
    __shared__ int carry_s;
    int tid = threadIdx.x, lane = tid & 31, wid = tid >> 5;
    if (tid == 0) carry_s = 0;
    __syncthreads();

    for (int base = 0; base < n; base += 1024) {
        int i = base + tid;
        int v = (i < n) ? hist[i] : 0;
        int incl = v;
        #pragma unroll
        for (int off = 1; off < 32; off <<= 1) {
            int t = __shfl_up_sync(0xFFFFFFFFu, incl, off);
            if (lane >= off) incl += t;
        }
        if (lane == 31) wsum[wid] = incl;
        __syncthreads();
        if (wid == 0) {
            int s = wsum[lane];
            #pragma unroll
            for (int off = 1; off < 32; off <<= 1) {
                int t = __shfl_up_sync(0xFFFFFFFFu, s, off);
                if (lane >= off) s += t;
            }
            wsum[lane] = s;
        }
        __syncthreads();
        int woff = wid ? wsum[wid - 1] : 0;
        int excl = carry_s + woff + incl - v;
        if (i < n) { rp[i] = excl; cur[i] = excl; }
        __syncthreads();
        if (tid == 1023) carry_s += woff + incl;
        __syncthreads();
    }
    if (threadIdx.x == 0) rp[n] = carry_s;
}

__global__ void scatter_kernel(const int* __restrict__ ei1,
                               const int* __restrict__ ei2,
                               const int* __restrict__ et2) {
    int i = blockIdx.x * blockDim.x + threadIdx.x;
    if (i >= EDGES) return;
    int s1 = ei1[i], d1 = ei1[EDGES + i];
    g_col1[atomicAdd(&g_cur1[d1], 1)] = s1;
    int s2 = ei2[i], d2 = ei2[EDGES + i], t = et2[i];
    g_col2[atomicAdd(&g_cur2[d2], 1)] = s2 | (t << 16);
}

// ------------------------------- concept ------------------------------------
__global__ void concept_kernel(const float4* __restrict__ x) {
    int gw = (blockIdx.x * blockDim.x + threadIdx.x) >> 5;
    if (gw >= N1) return;
    int lane = threadIdx.x & 31;
    int b = g_rp1[gw], e = g_rp1[gw + 1];
    float4 acc = make_float4(0.f, 0.f, 0.f, 0.f);
    for (int j = b; j < e; j++) {
        float4 xs = x[g_col1[j] * 32 + lane];
        acc.x += xs.x; acc.y += xs.y; acc.z += xs.z; acc.w += xs.w;
    }
    float inv = 1.f / (float)max(e - b, 1);
    float4 xv = x[gw * 32 + lane];
    float4 r;
    r.x = fmaxf(fmaf(acc.x, inv, xv.x), 0.f);
    r.y = fmaxf(fmaf(acc.y, inv, xv.y), 0.f);
    r.z = fmaxf(fmaf(acc.z, inv, xv.z), 0.f);
    r.w = fmaxf(fmaf(acc.w, inv, xv.w), 0.f);
    ((float4*)g_xg1)[gw * 32 + lane] = r;
}

// --------------------------- weights (bf16 split, transposed) ---------------
__device__ __forceinline__ void bsplit(float v, __nv_bfloat16& h, __nv_bfloat16& l) {
    h = __float2bfloat16(v);
    l = __float2bfloat16(v - __bfloat162float(h));
}

__global__ void wbuild_kernel(const float* __restrict__ root1, const float* __restrict__ b1,
                              const float* __restrict__ root2, const float* __restrict__ b2) {
    int i = blockIdx.x * blockDim.x + threadIdx.x;
    if (i >= DIMV * KTOT) return;
    int n = i / KTOT, k = i % KTOT;
    float v1 = (k < 128) ? root1[k * 128 + n] : b1[(k - 128) * 128 + n];
    float v2 = (k < 128) ? root2[k * 128 + n] : b2[(k - 128) * 128 + n];
    bsplit(v1, g_Wh[i], g_Wl[i]);
    bsplit(v2, g_Wh[DIMV * KTOT + i], g_Wl[DIMV * KTOT + i]);
}

// --------------------------- RGCN aggregation -------------------------------
__device__ __forceinline__ void split_store4(float4 v, size_t off) {
    __nv_bfloat16 hx, hy, hz, hw, lx, ly, lz, lw;
    bsplit(v.x, hx, lx); bsplit(v.y, hy, ly);
    bsplit(v.z, hz, lz); bsplit(v.w, hw, lw);
    uint2 H, L;
    H.x = (uint32_t)__bfloat16_as_ushort(hx) | ((uint32_t)__bfloat16_as_ushort(hy) << 16);
    H.y = (uint32_t)__bfloat16_as_ushort(hz) | ((uint32_t)__bfloat16_as_ushort(hw) << 16);
    L.x = (uint32_t)__bfloat16_as_ushort(lx) | ((uint32_t)__bfloat16_as_ushort(ly) << 16);
    L.y = (uint32_t)__bfloat16_as_ushort(lz) | ((uint32_t)__bfloat16_as_ushort(lw) << 16);
    *(uint2*)(g_Ah + off) = H;
    *(uint2*)(g_Al + off) = L;
}

__global__ void agg_kernel(int layer, const float* __restrict__ comp) {
    __shared__ float4 comps[NR];
    int tid = threadIdx.x;
    if (tid < NR)
        comps[tid] = make_float4(comp[tid * 4 + 0], comp[tid * 4 + 1],
                                 comp[tid * 4 + 2], comp[tid * 4 + 3]);
    __syncthreads();
    int gw = (blockIdx.x * blockDim.x + tid) >> 5;
    if (gw >= N2) return;
    int lane = tid & 31;
    const float4* x = layer ? (const float4*)g_xa : (const float4*)g_xg1;

    float nrm = 0.f;
    if (lane < NR) nrm = 1.f / (float)max(g_cseg[gw * NR + lane], 1);

    int b = g_rp2[gw], e = g_rp2[gw + 1];
    float4 a0 = make_float4(0.f, 0.f, 0.f, 0.f);
    float4 a1 = a0, a2 = a0, a3 = a0;
    for (int j = b; j < e; j++) {
        int pk = g_col2[j];
        int s = pk & 0xFFFF;
        int et = pk >> 16;
        float nz = __shfl_sync(0xFFFFFFFFu, nrm, et);
        float4 c4 = comps[et];
        float4 xs = x[s * 32 + lane];
        float c0 = c4.x * nz, c1 = c4.y * nz, c2 = c4.z * nz, c3 = c4.w * nz;
        a0.x = fmaf(c0, xs.x, a0.x); a0.y = fmaf(c0, xs.y, a0.y);
        a0.z = fmaf(c0, xs.z, a0.z); a0.w = fmaf(c0, xs.w, a0.w);
        a1.x = fmaf(c1, xs.x, a1.x); a1.y = fmaf(c1, xs.y, a1.y);
        a1.z = fmaf(c1, xs.z, a1.z); a1.w = fmaf(c1, xs.w, a1.w);
        a2.x = fmaf(c2, xs.x, a2.x); a2.y = fmaf(c2, xs.y, a2.y);
        a2.z = fmaf(c2, xs.z, a2.z); a2.w = fmaf(c2, xs.w, a2.w);
        a3.x = fmaf(c3, xs.x, a3.x); a3.y = fmaf(c3, xs.y, a3.y);
        a3.z = fmaf(c3, xs.z, a3.z); a3.w = fmaf(c3, xs.w, a3.w);
    }
    size_t base = (size_t)gw * KTOT + lane * 4;
    split_store4(x[gw * 32 + lane], base);
    split_store4(a0, base + 128);
    split_store4(a1, base + 256);
    split_store4(a2, base + 384);
    split_store4(a3, base + 512);
}

// --------------------------- HMMA split-bf16 GEMM ---------------------------
// C[M x 128] = A[M x 640] @ Wt^T + bias   via  Ah*Bh + Ah*Bl + Al*Bh
// mma.sync.m16n8k16 row.col bf16; B stored [n][k] = col-major B.
#define KC 64            // K chunk (bf16 elems)
#define SROW 72          // smem row stride in bf16 (conflict-free: bank=(4r+q)%32)
#define SROW4 9          // row stride in uint4
#define SBUF (128 * SROW)  // bf16 elems per buffer

__device__ __forceinline__ void mma_bf16(float* c, const uint32_t* a, const uint32_t* b) {
    asm volatile(
        "mma.sync.aligned.m16n8k16.row.col.f32.bf16.bf16.f32 "
        "{%0,%1,%2,%3}, {%4,%5,%6,%7}, {%8,%9}, {%0,%1,%2,%3};"
        : "+f"(c[0]), "+f"(c[1]), "+f"(c[2]), "+f"(c[3])
        : "r"(a[0]), "r"(a[1]), "r"(a[2]), "r"(a[3]), "r"(b[0]), "r"(b[1]));
}

__global__ __launch_bounds__(256, 1) void mma_gemm_kernel(int layer,
                                                          const float* __restrict__ bias,
                                                          int relu) {
    extern __shared__ __nv_bfloat16 sm[];
    __nv_bfloat16* sAh = sm;
    __nv_bfloat16* sAl = sm + SBUF;
    __nv_bfloat16* sBh = sm + 2 * SBUF;
    __nv_bfloat16* sBl = sm + 3 * SBUF;

    const int tid = threadIdx.x;
    const int wid = tid >> 5, lane = tid & 31;
    const int m0 = blockIdx.x * 128;
    const int m0w = (wid >> 2) * 64;      // warp m offset (0 or 64)
    const int n0w = (wid & 3) * 32;       // warp n offset (0,32,64,96)
    const int r = lane >> 2, q = lane & 3;

    const uint4* pAH = (const uint4*)g_Ah;                          // row stride 80 uint4
    const uint4* pAL = (const uint4*)g_Al;
    const uint4* pWH = (const uint4*)(g_Wh + (size_t)layer * DIMV * KTOT);
    const uint4* pWL = (const uint4*)(g_Wl + (size_t)layer * DIMV * KTOT);
    float* C = layer ? g_xb : g_xa;

    float acc[4][4][4];
    #pragma unroll
    for (int i = 0; i < 4; i++)
        #pragma unroll
        for (int j = 0; j < 4; j++)
            #pragma unroll
            for (int k = 0; k < 4; k++) acc[i][j][k] = 0.f;

    const uint4 zz = make_uint4(0, 0, 0, 0);

    for (int c = 0; c < KTOT / KC; c++) {
        const int kb = c * (KC / 8);      // uint4 col base in gmem row
        // ---- stage 4 buffers: 1024 uint4 each, 4 per thread per buffer ----
        #pragma unroll
        for (int j = 0; j < 4; j++) {
            int idx = tid + j * 256;
            int row = idx >> 3, col = idx & 7;
            uint4* dst = (uint4*)(sAh) + row * SROW4 + col;
            uint4* dstL = (uint4*)(sAl) + row * SROW4 + col;
            int m = m0 + row;
            uint4 vh = zz, vl = zz;
            if (m < N2) {
                size_t go = (size_t)m * 80 + kb + col;
                vh = pAH[go];
                vl = pAL[go];
            }
            *dst = vh;
            *dstL = vl;
            size_t wo = (size_t)row * 80 + kb + col;
            *((uint4*)(sBh) + row * SROW4 + col) = pWH[wo];
            *((uint4*)(sBl) + row * SROW4 + col) = pWL[wo];
        }
        __syncthreads();

        const uint32_t* Ah32 = (const uint32_t*)sAh;
        const uint32_t* Al32 = (const uint32_t*)sAl;
        const uint32_t* Bh32 = (const uint32_t*)sBh;
        const uint32_t* Bl32 = (const uint32_t*)sBl;

        #pragma unroll
        for (int kk = 0; kk < KC; kk += 16) {
            const int kw = kk >> 1;       // word offset of k16 step
            uint32_t ah[4][4], al[4][4], bh[4][2], bl[4][2];
            #pragma unroll
            for (int mt = 0; mt < 4; mt++) {
                int row0 = (m0w + mt * 16 + r) * (SROW / 2);
                int row8 = row0 + 8 * (SROW / 2);
                ah[mt][0] = Ah32[row0 + kw + q];
                ah[mt][1] = Ah32[row8 + kw + q];
                ah[mt][2] = Ah32[row0 + kw + 4 + q];
                ah[mt][3] = Ah32[row8 + kw + 4 + q];
                al[mt][0] = Al32[row0 + kw + q];
                al[mt][1] = Al32[row8 + kw + q];
                al[mt][2] = Al32[row0 + kw + 4 + q];
                al[mt][3] = Al32[row8 + kw + 4 + q];
            }
            #pragma unroll
            for (int nt = 0; nt < 4; nt++) {
                int nrow = (n0w + nt * 8 + r) * (SROW / 2);
                bh[nt][0] = Bh32[nrow + kw + q];
                bh[nt][1] = Bh32[nrow + kw + 4 + q];
                bl[nt][0] = Bl32[nrow + kw + q];
                bl[nt][1] = Bl32[nrow + kw + 4 + q];
            }
            #pragma unroll
            for (int mt = 0; mt < 4; mt++)
                #pragma unroll
                for (int nt = 0; nt < 4; nt++) {
                    mma_bf16(acc[mt][nt], ah[mt], bh[nt]);
                    mma_bf16(acc[mt][nt], ah[mt], bl[nt]);
                    mma_bf16(acc[mt][nt], al[mt], bh[nt]);
                }
        }
        __syncthreads();
    }

    // ---------------- epilogue: bias + optional relu, direct stores ----------
    #pragma unroll
    for (int nt = 0; nt < 4; nt++) {
        int col = n0w + nt * 8 + q * 2;
        float b0 = bias[col], b1 = bias[col + 1];
        #pragma unroll
        for (int mt = 0; mt < 4; mt++) {
            int row = m0 + m0w + mt * 16 + r;
            float2 v0, v1;
            v0.x = acc[mt][nt][0] + b0; v0.y = acc[mt][nt][1] + b1;
            v1.x = acc[mt][nt][2] + b0; v1.y = acc[mt][nt][3] + b1;
            if (relu) {
                v0.x = fmaxf(v0.x, 0.f); v0.y = fmaxf(v0.y, 0.f);
                v1.x = fmaxf(v1.x, 0.f); v1.y = fmaxf(v1.y, 0.f);
            }
            if (row < N2)     *(float2*)(C + (size_t)row * DIMV + col) = v0;
            if (row + 8 < N2) *(float2*)(C + (size_t)(row + 8) * DIMV + col) = v1;
        }
    }
}

// ------------------------------ logits --------------------------------------
__global__ void tyw_kernel(const int* __restrict__ lc, const float* __restrict__ w) {
    int i = blockIdx.x * blockDim.x + threadIdx.x;
    if (i >= DIMV * LCN) return;
    int d = i / LCN, l = i % LCN;
    g_tywT[i] = g_xg1[(size_t)lc[l] * DIMV + d] * w[d];
}

__global__ void logits_kernel(float* __restrict__ out) {
    extern __shared__ float sh[];
    float* tw = sh;
    float* xr = sh + DIMV * LCN;
    int tid = threadIdx.x;
    for (int i = tid; i < DIMV * LCN; i += blockDim.x) tw[i] = g_tywT[i];
    __syncthreads();
    int lane = tid & 31, wid = tid >> 5;
    const float4* xg2 = (const float4*)g_xb;

    for (int row = blockIdx.x * 8 + wid; row < N2; row += gridDim.x * 8) {
        float4 xv = xg2[row * 32 + lane];
        *(float4*)&xr[wid * 128 + lane * 4] = xv;
        __syncwarp();
        float d0 = 0.f, d1 = 0.f, d2 = 0.f, d3 = 0.f;
        #pragma unroll 4
        for (int d = 0; d < DIMV; d++) {
            float xd = xr[wid * 128 + d];
            d0 = fmaf(xd, tw[d * LCN + lane], d0);
            d1 = fmaf(xd, tw[d * LCN + lane + 32], d1);
            d2 = fmaf(xd, tw[d * LCN + lane + 64], d2);
            float t3 = (lane < 4) ? tw[d * LCN + lane + 96] : 0.f;
            d3 = fmaf(xd, t3, d3);
        }
        float d3m = (lane < 4) ? d3 : -1e30f;
        float mx = fmaxf(fmaxf(d0, d1), fmaxf(d2, d3m));
        #pragma unroll
        for (int off = 16; off > 0; off >>= 1)
            mx = fmaxf(mx, __shfl_xor_sync(0xFFFFFFFFu, mx, off));
        float e0 = expf(d0 - mx), e1 = expf(d1 - mx), e2 = expf(d2 - mx);
        float e3 = (lane < 4) ? expf(d3 - mx) : 0.f;
        float s = e0 + e1 + e2 + e3;
        #pragma unroll
        for (int off = 16; off > 0; off >>= 1)
            s += __shfl_xor_sync(0xFFFFFFFFu, s, off);
        float inv = 1.f / s;
        float* orow = out + (size_t)row * LCN;
        orow[lane] = e0 * inv;
        orow[lane + 32] = e1 * inv;
        orow[lane + 64] = e2 * inv;
        if (lane < 4) orow[lane + 96] = e3 * inv;
        __syncwarp();
    }
}

// ------------------------------- launcher -----------------------------------
extern "C" void kernel_launch(void* const* d_in, const int* in_sizes, int n_in,
                              void* d_out, int out_size) {
    const int* ei2 = (const int*)d_in[0];
    const int* et2 = (const int*)d_in[1];
    const int* ei1 = (const int*)d_in[2];
    const int* lc  = (const int*)d_in[3];
    const float* x0     = (const float*)d_in[4];
    const float* basis1 = (const float*)d_in[5];
    const float* comp1  = (const float*)d_in[6];
    const float* root1  = (const float*)d_in[7];
    const float* bias1  = (const float*)d_in[8];
    const float* basis2 = (const float*)d_in[9];
    const float* comp2  = (const float*)d_in[10];
    const float* root2  = (const float*)d_in[11];
    const float* bias2  = (const float*)d_in[12];
    const float* w      = (const float*)d_in[13];
    float* out = (float*)d_out;

    const int GEMM_SMEM = 4 * SBUF * (int)sizeof(__nv_bfloat16);  // 73728
    cudaFuncSetAttribute(mma_gemm_kernel, cudaFuncAttributeMaxDynamicSharedMemorySize,
                         GEMM_SMEM);
    const int LOGITS_SMEM = (DIMV * LCN + 8 * 128) * sizeof(float);  // 55296 B
    cudaFuncSetAttribute(logits_kernel, cudaFuncAttributeMaxDynamicSharedMemorySize,
                         LOGITS_SMEM);

    zero_kernel<<<(N2 * NR + 255) / 256, 256>>>();
    hist_kernel<<<(EDGES + 255) / 256, 256>>>(ei1, ei2, et2);
    scan_kernel<<<2, 1024>>>();
    scatter_kernel<<<(EDGES + 255) / 256, 256>>>(ei1, ei2, et2);
    concept_kernel<<<N1 / 8, 256>>>((const float4*)x0);
    wbuild_kernel<<<(DIMV * KTOT + 255) / 256, 256>>>(root1, basis1, root2, basis2);

    agg_kernel<<<N2 / 8, 256>>>(0, comp1);
    mma_gemm_kernel<<<(N2 + 127) / 128, 256, GEMM_SMEM>>>(0, bias1, 1);
    agg_kernel<<<N2 / 8, 256>>>(1, comp2);
    mma_gemm_kernel<<<(N2 + 127) / 128, 256, GEMM_SMEM>>>(1, bias2, 0);

    tyw_kernel<<<(DIMV * LCN + 255) / 256, 256>>>(lc, w);
    logits_kernel<<<296, 256, LOGITS_SMEM>>>(out);
}

// round 4
// speedup vs baseline: 1.8669x; 1.1506x over previous
#include <cuda_runtime.h>
#include <cuda_bf16.h>
#include <cstdint>

#define N1 60000
#define N2 50000
#define EDGES 800000
#define DIMV 128
#define NR 16
#define LCN 100
#define KTOT 640
#define P1BLKS 59   // ceil(60000/1024)
#define P2BLKS 49   // ceil(50000/1024)
#define NPBLKS (P1BLKS + P2BLKS)

// ------------------------- scratch (device globals) -------------------------
__device__ float g_xg1[N1 * DIMV];                 // concept-layer output (relu'd)
__device__ __nv_bfloat16 g_Ah[N2 * KTOT];          // [x | agg4] hi (bf16)
__device__ __nv_bfloat16 g_Al[N2 * KTOT];          // [x | agg4] lo (bf16)
__device__ float g_xa[N2 * DIMV];                  // rgcn1 output (relu'd)
__device__ float g_xb[N2 * DIMV];                  // rgcn2 output
__device__ __nv_bfloat16 g_Wh[2 * DIMV * KTOT];    // Wt[n][k] hi, both layers
__device__ __nv_bfloat16 g_Wl[2 * DIMV * KTOT];    // Wt[n][k] lo
__device__ float g_tywT[DIMV * LCN];               // (ty * w)^T  [d][l]
__device__ int g_hist1[N1];
__device__ int g_rp1[N1 + 1];
__device__ int g_cur1[N1];
__device__ int g_col1[EDGES];
__device__ int g_hist2[N2];
__device__ int g_rp2[N2 + 1];
__device__ int g_cur2[N2];
__device__ int g_col2[EDGES];                      // packed: src | (etype<<16)
__device__ int g_cseg[N2 * NR];
__device__ int g_part[NPBLKS];
__device__ int g_partsum[NPBLKS];

// ------------------------------- CSR build ----------------------------------
__global__ void zero_kernel() {
    int i = blockIdx.x * blockDim.x + threadIdx.x;
    if (i < N1) g_hist1[i] = 0;
    if (i < N2) g_hist2[i] = 0;
    if (i < N2 * NR) g_cseg[i] = 0;
}

__global__ void hist_kernel(const int* __restrict__ ei1,
                            const int* __restrict__ ei2,
                            const int* __restrict__ et2) {
    int i = blockIdx.x * blockDim.x + threadIdx.x;
    if (i >= EDGES) return;
    atomicAdd(&g_hist1[ei1[EDGES + i]], 1);
    int d2 = ei2[EDGES + i];
    atomicAdd(&g_hist2[d2], 1);
    atomicAdd(&g_cseg[d2 * NR + et2[i]], 1);
}

// ---- 3-phase scan: block-local scan -> partials scan -> add offsets --------
__global__ void scan_p1() {
    int b = blockIdx.x;
    const int* arr;
    int n, base;
    int* rp;
    if (b < P1BLKS) { arr = g_hist1; n = N1; base = b << 10; rp = g_rp1; }
    else { arr = g_hist2; n = N2; base = (b - P1BLKS) << 10; rp = g_rp2; }
    int tid = threadIdx.x, lane = tid & 31, wid = tid >> 5;
    __shared__ int wsum[32];
    int i = base + tid;
    int v = (i < n) ? arr[i] : 0;
    int inc = v;
    #pragma unroll
    for (int off = 1; off < 32; off <<= 1) {
        int t = __shfl_up_sync(0xFFFFFFFFu, inc, off);
        if (lane >= off) inc += t;
    }
    if (lane == 31) wsum[wid] = inc;
    __syncthreads();
    if (wid == 0) {
        int s = wsum[lane];
        #pragma unroll
        for (int off = 1; off < 32; off <<= 1) {
            int t = __shfl_up_sync(0xFFFFFFFFu, s, off);
            if (lane >= off) s += t;
        }
        wsum[lane] = s;
    }
    __syncthreads();
    int woff = wid ? wsum[wid - 1] : 0;
    if (i < n) rp[i] = woff + inc - v;
    if (tid == 1023) g_part[b] = woff + inc;
}

__global__ void scan_p2() {
    int tid = threadIdx.x, lane = tid & 31, wid = tid >> 5;
    int off = wid ? P1BLKS : 0;
    int cnt = wid ? P2BLKS : P1BLKS;
    int carry = 0;
    for (int base = 0; base < cnt; base += 32) {
        int k = base + lane;
        int v = (k < cnt) ? g_part[off + k] : 0;
        int inc = v;
        #pragma unroll
        for (int o = 1; o < 32; o <<= 1) {
            int t = __shfl_up_sync(0xFFFFFFFFu, inc, o);
            if (lane >= o) inc += t;
        }
        if (k < cnt) g_partsum[off + k] = carry + inc - v;
        carry += __shfl_sync(0xFFFFFFFFu, inc, 31);
    }
    if (lane == 0) {
        if (wid == 0) g_rp1[N1] = carry;
        else g_rp2[N2] = carry;
    }
}

__global__ void scan_p3() {
    int b = blockIdx.x;
    int n, base;
    int *rp, *cur;
    if (b < P1BLKS) { n = N1; base = b << 10; rp = g_rp1; cur = g_cur1; }
    else { n = N2; base = (b - P1BLKS) << 10; rp = g_rp2; cur = g_cur2; }
    int i = base + threadIdx.x;
    if (i < n) {
        int v = rp[i] + g_partsum[b];
        rp[i] = v;
        cur[i] = v;
    }
}

__global__ void scatter_kernel(const int* __restrict__ ei1,
                               const int* __restrict__ ei2,
                               const int* __restrict__ et2) {
    int i = blockIdx.x * blockDim.x + threadIdx.x;
    if (i >= EDGES) return;
    int s1 = ei1[i], d1 = ei1[EDGES + i];
    g_col1[atomicAdd(&g_cur1[d1], 1)] = s1;
    int s2 = ei2[i], d2 = ei2[EDGES + i], t = et2[i];
    g_col2[atomicAdd(&g_cur2[d2], 1)] = s2 | (t << 16);
}

// ------------------------------- concept ------------------------------------
__global__ void concept_kernel(const float4* __restrict__ x) {
    int gw = (blockIdx.x * blockDim.x + threadIdx.x) >> 5;
    if (gw >= N1) return;
    int lane = threadIdx.x & 31;
    int b = g_rp1[gw], e = g_rp1[gw + 1];
    float4 acc = make_float4(0.f, 0.f, 0.f, 0.f);
    float4 acc2 = acc;
    int j = b;
    for (; j + 2 <= e; j += 2) {
        int s0 = g_col1[j], s1 = g_col1[j + 1];
        float4 x0 = x[s0 * 32 + lane];
        float4 x1 = x[s1 * 32 + lane];
        acc.x += x0.x; acc.y += x0.y; acc.z += x0.z; acc.w += x0.w;
        acc2.x += x1.x; acc2.y += x1.y; acc2.z += x1.z; acc2.w += x1.w;
    }
    if (j < e) {
        float4 x0 = x[g_col1[j] * 32 + lane];
        acc.x += x0.x; acc.y += x0.y; acc.z += x0.z; acc.w += x0.w;
    }
    acc.x += acc2.x; acc.y += acc2.y; acc.z += acc2.z; acc.w += acc2.w;
    float inv = 1.f / (float)max(e - b, 1);
    float4 xv = x[gw * 32 + lane];
    float4 r;
    r.x = fmaxf(fmaf(acc.x, inv, xv.x), 0.f);
    r.y = fmaxf(fmaf(acc.y, inv, xv.y), 0.f);
    r.z = fmaxf(fmaf(acc.z, inv, xv.z), 0.f);
    r.w = fmaxf(fmaf(acc.w, inv, xv.w), 0.f);
    ((float4*)g_xg1)[gw * 32 + lane] = r;
}

// --------------------------- weights (bf16 split, transposed) ---------------
__device__ __forceinline__ void bsplit(float v, __nv_bfloat16& h, __nv_bfloat16& l) {
    h = __float2bfloat16(v);
    l = __float2bfloat16(v - __bfloat162float(h));
}

__global__ void wbuild_kernel(const float* __restrict__ root1, const float* __restrict__ b1,
                              const float* __restrict__ root2, const float* __restrict__ b2) {
    int i = blockIdx.x * blockDim.x + threadIdx.x;
    if (i >= DIMV * KTOT) return;
    int n = i / KTOT, k = i % KTOT;
    float v1 = (k < 128) ? root1[k * 128 + n] : b1[(k - 128) * 128 + n];
    float v2 = (k < 128) ? root2[k * 128 + n] : b2[(k - 128) * 128 + n];
    bsplit(v1, g_Wh[i], g_Wl[i]);
    bsplit(v2, g_Wh[DIMV * KTOT + i], g_Wl[DIMV * KTOT + i]);
}

// --------------------------- RGCN aggregation -------------------------------
__device__ __forceinline__ void split_store4(float4 v, size_t off) {
    __nv_bfloat16 hx, hy, hz, hw, lx, ly, lz, lw;
    bsplit(v.x, hx, lx); bsplit(v.y, hy, ly);
    bsplit(v.z, hz, lz); bsplit(v.w, hw, lw);
    uint2 H, L;
    H.x = (uint32_t)__bfloat16_as_ushort(hx) | ((uint32_t)__bfloat16_as_ushort(hy) << 16);
    H.y = (uint32_t)__bfloat16_as_ushort(hz) | ((uint32_t)__bfloat16_as_ushort(hw) << 16);
    L.x = (uint32_t)__bfloat16_as_ushort(lx) | ((uint32_t)__bfloat16_as_ushort(ly) << 16);
    L.y = (uint32_t)__bfloat16_as_ushort(lz) | ((uint32_t)__bfloat16_as_ushort(lw) << 16);
    *(uint2*)(g_Ah + off) = H;
    *(uint2*)(g_Al + off) = L;
}

__device__ __forceinline__ void agg_fma(float4& a0, float4& a1, float4& a2, float4& a3,
                                        float4 c4, float nz, float4 xs) {
    float c0 = c4.x * nz, c1 = c4.y * nz, c2 = c4.z * nz, c3 = c4.w * nz;
    a0.x = fmaf(c0, xs.x, a0.x); a0.y = fmaf(c0, xs.y, a0.y);
    a0.z = fmaf(c0, xs.z, a0.z); a0.w = fmaf(c0, xs.w, a0.w);
    a1.x = fmaf(c1, xs.x, a1.x); a1.y = fmaf(c1, xs.y, a1.y);
    a1.z = fmaf(c1, xs.z, a1.z); a1.w = fmaf(c1, xs.w, a1.w);
    a2.x = fmaf(c2, xs.x, a2.x); a2.y = fmaf(c2, xs.y, a2.y);
    a2.z = fmaf(c2, xs.z, a2.z); a2.w = fmaf(c2, xs.w, a2.w);
    a3.x = fmaf(c3, xs.x, a3.x); a3.y = fmaf(c3, xs.y, a3.y);
    a3.z = fmaf(c3, xs.z, a3.z); a3.w = fmaf(c3, xs.w, a3.w);
}

__global__ void agg_kernel(int layer, const float* __restrict__ comp) {
    __shared__ float4 comps[NR];
    int tid = threadIdx.x;
    if (tid < NR)
        comps[tid] = make_float4(comp[tid * 4 + 0], comp[tid * 4 + 1],
                                 comp[tid * 4 + 2], comp[tid * 4 + 3]);
    __syncthreads();
    int gw = (blockIdx.x * blockDim.x + tid) >> 5;
    if (gw >= N2) return;
    int lane = tid & 31;
    const float4* x = layer ? (const float4*)g_xa : (const float4*)g_xg1;

    float nrm = 0.f;
    if (lane < NR) nrm = 1.f / (float)max(g_cseg[gw * NR + lane], 1);

    int b = g_rp2[gw], e = g_rp2[gw + 1];
    float4 a0 = make_float4(0.f, 0.f, 0.f, 0.f);
    float4 a1 = a0, a2 = a0, a3 = a0;
    int j = b;
    for (; j + 2 <= e; j += 2) {
        int pk0 = g_col2[j], pk1 = g_col2[j + 1];
        int s0 = pk0 & 0xFFFF, t0 = pk0 >> 16;
        int s1 = pk1 & 0xFFFF, t1 = pk1 >> 16;
        float4 x0 = x[s0 * 32 + lane];
        float4 x1 = x[s1 * 32 + lane];
        float nz0 = __shfl_sync(0xFFFFFFFFu, nrm, t0);
        float nz1 = __shfl_sync(0xFFFFFFFFu, nrm, t1);
        agg_fma(a0, a1, a2, a3, comps[t0], nz0, x0);
        agg_fma(a0, a1, a2, a3, comps[t1], nz1, x1);
    }
    if (j < e) {
        int pk = g_col2[j];
        int s = pk & 0xFFFF, t = pk >> 16;
        float nz = __shfl_sync(0xFFFFFFFFu, nrm, t);
        agg_fma(a0, a1, a2, a3, comps[t], nz, x[s * 32 + lane]);
    }
    size_t base = (size_t)gw * KTOT + lane * 4;
    split_store4(x[gw * 32 + lane], base);
    split_store4(a0, base + 128);
    split_store4(a1, base + 256);
    split_store4(a2, base + 384);
    split_store4(a3, base + 512);
}

// --------------------------- HMMA split-bf16 GEMM ---------------------------
// C[M x 128] = A[M x 640] @ Wt^T + bias   via  Ah*Bh + Ah*Bl + Al*Bh
// mma.sync.m16n8k16 row.col bf16; B stored [n][k] = col-major B.
// 2-stage cp.async pipeline.
#define KC 64              // K chunk (bf16 elems)
#define SROW 72            // smem row stride in bf16 (conflict-free)
#define SROW4 9            // row stride in uint4
#define SBUF (128 * SROW)  // bf16 elems per buffer (9216)
#define STGB (4 * SBUF * 2)  // bytes per stage (73728)
#define BUFB (SBUF * 2)      // bytes per buffer (18432)

__device__ __forceinline__ void mma_bf16(float* c, const uint32_t* a, const uint32_t* b) {
    asm volatile(
        "mma.sync.aligned.m16n8k16.row.col.f32.bf16.bf16.f32 "
        "{%0,%1,%2,%3}, {%4,%5,%6,%7}, {%8,%9}, {%0,%1,%2,%3};"
        : "+f"(c[0]), "+f"(c[1]), "+f"(c[2]), "+f"(c[3])
        : "r"(a[0]), "r"(a[1]), "r"(a[2]), "r"(a[3]), "r"(b[0]), "r"(b[1]));
}

__device__ __forceinline__ void cp16(uint32_t saddr, const void* g, bool pred) {
    int sz = pred ? 16 : 0;
    asm volatile("cp.async.cg.shared.global [%0], [%1], 16, %2;"
                 :: "r"(saddr), "l"(g), "r"(sz));
}

__global__ __launch_bounds__(256, 1) void mma_gemm_kernel(int layer,
                                                          const float* __restrict__ bias,
                                                          int relu) {
    extern __shared__ __nv_bfloat16 sm[];

    const int tid = threadIdx.x;
    const int wid = tid >> 5, lane = tid & 31;
    const int m0 = blockIdx.x * 128;
    const int m0w = (wid >> 2) * 64;      // warp m offset (0 or 64)
    const int n0w = (wid & 3) * 32;       // warp n offset (0,32,64,96)
    const int r = lane >> 2, q = lane & 3;

    const uint4* pAH = (const uint4*)g_Ah;                          // row stride 80 uint4
    const uint4* pAL = (const uint4*)g_Al;
    const uint4* pWH = (const uint4*)(g_Wh + (size_t)layer * DIMV * KTOT);
    const uint4* pWL = (const uint4*)(g_Wl + (size_t)layer * DIMV * KTOT);
    float* C = layer ? g_xb : g_xa;

    uint32_t sbase = (uint32_t)__cvta_generic_to_shared(sm);

    float acc[4][4][4];
    #pragma unroll
    for (int i = 0; i < 4; i++)
        #pragma unroll
        for (int j = 0; j < 4; j++)
            #pragma unroll
            for (int k = 0; k < 4; k++) acc[i][j][k] = 0.f;

    // ---------------- stage chunk loader (cp.async) ----------------
    auto stage_load = [&](int c, int s) {
        const int kb = c * 8;             // uint4 col base in gmem row
        uint32_t st = sbase + (uint32_t)s * STGB;
        #pragma unroll
        for (int j = 0; j < 4; j++) {
            int idx = tid + j * 256;
            int row = idx >> 3, col = idx & 7;
            uint32_t so = (uint32_t)(row * SROW4 + col) * 16;
            int m = m0 + row;
            bool ok = m < N2;
            size_t ga = (size_t)(ok ? m : 0) * 80 + kb + col;
            cp16(st + so, pAH + ga, ok);
            cp16(st + BUFB + so, pAL + ga, ok);
            size_t wo = (size_t)row * 80 + kb + col;
            cp16(st + 2 * BUFB + so, pWH + wo, true);
            cp16(st + 3 * BUFB + so, pWL + wo, true);
        }
        asm volatile("cp.async.commit_group;");
    };

    stage_load(0, 0);
    for (int c = 0; c < KTOT / KC; c++) {
        if (c < KTOT / KC - 1) {
            stage_load(c + 1, (c + 1) & 1);
            asm volatile("cp.async.wait_group 1;");
        } else {
            asm volatile("cp.async.wait_group 0;");
        }
        __syncthreads();

        const __nv_bfloat16* sbuf = sm + (size_t)(c & 1) * (4 * SBUF);
        const uint32_t* Ah32 = (const uint32_t*)sbuf;
        const uint32_t* Al32 = (const uint32_t*)(sbuf + SBUF);
        const uint32_t* Bh32 = (const uint32_t*)(sbuf + 2 * SBUF);
        const uint32_t* Bl32 = (const uint32_t*)(sbuf + 3 * SBUF);

        #pragma unroll
        for (int kk = 0; kk < KC; kk += 16) {
            const int kw = kk >> 1;       // word offset of k16 step
            uint32_t ah[4][4], al[4][4], bh[4][2], bl[4][2];
            #pragma unroll
            for (int mt = 0; mt < 4; mt++) {
                int row0 = (m0w + mt * 16 + r) * (SROW / 2);
                int row8 = row0 + 8 * (SROW / 2);
                ah[mt][0] = Ah32[row0 + kw + q];
                ah[mt][1] = Ah32[row8 + kw + q];
                ah[mt][2] = Ah32[row0 + kw + 4 + q];
                ah[mt][3] = Ah32[row8 + kw + 4 + q];
                al[mt][0] = Al32[row0 + kw + q];
                al[mt][1] = Al32[row8 + kw + q];
                al[mt][2] = Al32[row0 + kw + 4 + q];
                al[mt][3] = Al32[row8 + kw + 4 + q];
            }
            #pragma unroll
            for (int nt = 0; nt < 4; nt++) {
                int nrow = (n0w + nt * 8 + r) * (SROW / 2);
                bh[nt][0] = Bh32[nrow + kw + q];
                bh[nt][1] = Bh32[nrow + kw + 4 + q];
                bl[nt][0] = Bl32[nrow + kw + q];
                bl[nt][1] = Bl32[nrow + kw + 4 + q];
            }
            #pragma unroll
            for (int mt = 0; mt < 4; mt++)
                #pragma unroll
                for (int nt = 0; nt < 4; nt++) {
                    mma_bf16(acc[mt][nt], ah[mt], bh[nt]);
                    mma_bf16(acc[mt][nt], ah[mt], bl[nt]);
                    mma_bf16(acc[mt][nt], al[mt], bh[nt]);
                }
        }
        __syncthreads();
    }

    // ---------------- epilogue: bias + optional relu, direct stores ----------
    #pragma unroll
    for (int nt = 0; nt < 4; nt++) {
        int col = n0w + nt * 8 + q * 2;
        float b0 = bias[col], b1 = bias[col + 1];
        #pragma unroll
        for (int mt = 0; mt < 4; mt++) {
            int row = m0 + m0w + mt * 16 + r;
            float2 v0, v1;
            v0.x = acc[mt][nt][0] + b0; v0.y = acc[mt][nt][1] + b1;
            v1.x = acc[mt][nt][2] + b0; v1.y = acc[mt][nt][3] + b1;
            if (relu) {
                v0.x = fmaxf(v0.x, 0.f); v0.y = fmaxf(v0.y, 0.f);
                v1.x = fmaxf(v1.x, 0.f); v1.y = fmaxf(v1.y, 0.f);
            }
            if (row < N2)     *(float2*)(C + (size_t)row * DIMV + col) = v0;
            if (row + 8 < N2) *(float2*)(C + (size_t)(row + 8) * DIMV + col) = v1;
        }
    }
}

// ------------------------------ logits --------------------------------------
__global__ void tyw_kernel(const int* __restrict__ lc, const float* __restrict__ w) {
    int i = blockIdx.x * blockDim.x + threadIdx.x;
    if (i >= DIMV * LCN) return;
    int d = i / LCN, l = i % LCN;
    g_tywT[i] = g_xg1[(size_t)lc[l] * DIMV + d] * w[d];
}

__global__ void logits_kernel(float* __restrict__ out) {
    extern __shared__ float sh[];
    float* tw = sh;
    float* xr = sh + DIMV * LCN;
    int tid = threadIdx.x;
    for (int i = tid; i < DIMV * LCN; i += blockDim.x) tw[i] = g_tywT[i];
    __syncthreads();
    int lane = tid & 31, wid = tid >> 5;
    const float4* xg2 = (const float4*)g_xb;

    for (int row = blockIdx.x * 8 + wid; row < N2; row += gridDim.x * 8) {
        float4 xv = xg2[row * 32 + lane];
        *(float4*)&xr[wid * 128 + lane * 4] = xv;
        __syncwarp();
        float d0 = 0.f, d1 = 0.f, d2 = 0.f, d3 = 0.f;
        #pragma unroll 4
        for (int d = 0; d < DIMV; d++) {
            float xd = xr[wid * 128 + d];
            d0 = fmaf(xd, tw[d * LCN + lane], d0);
            d1 = fmaf(xd, tw[d * LCN + lane + 32], d1);
            d2 = fmaf(xd, tw[d * LCN + lane + 64], d2);
            float t3 = (lane < 4) ? tw[d * LCN + lane + 96] : 0.f;
            d3 = fmaf(xd, t3, d3);
        }
        float d3m = (lane < 4) ? d3 : -1e30f;
        float mx = fmaxf(fmaxf(d0, d1), fmaxf(d2, d3m));
        #pragma unroll
        for (int off = 16; off > 0; off >>= 1)
            mx = fmaxf(mx, __shfl_xor_sync(0xFFFFFFFFu, mx, off));
        float e0 = expf(d0 - mx), e1 = expf(d1 - mx), e2 = expf(d2 - mx);
        float e3 = (lane < 4) ? expf(d3 - mx) : 0.f;
        float s = e0 + e1 + e2 + e3;
        #pragma unroll
        for (int off = 16; off > 0; off >>= 1)
            s += __shfl_xor_sync(0xFFFFFFFFu, s, off);
        float inv = 1.f / s;
        float* orow = out + (size_t)row * LCN;
        orow[lane] = e0 * inv;
        orow[lane + 32] = e1 * inv;
        orow[lane + 64] = e2 * inv;
        if (lane < 4) orow[lane + 96] = e3 * inv;
        __syncwarp();
    }
}

// ------------------------------- launcher -----------------------------------
extern "C" void kernel_launch(void* const* d_in, const int* in_sizes, int n_in,
                              void* d_out, int out_size) {
    const int* ei2 = (const int*)d_in[0];
    const int* et2 = (const int*)d_in[1];
    const int* ei1 = (const int*)d_in[2];
    const int* lc  = (const int*)d_in[3];
    const float* x0     = (const float*)d_in[4];
    const float* basis1 = (const float*)d_in[5];
    const float* comp1  = (const float*)d_in[6];
    const float* root1  = (const float*)d_in[7];
    const float* bias1  = (const float*)d_in[8];
    const float* basis2 = (const float*)d_in[9];
    const float* comp2  = (const float*)d_in[10];
    const float* root2  = (const float*)d_in[11];
    const float* bias2  = (const float*)d_in[12];
    const float* w      = (const float*)d_in[13];
    float* out = (float*)d_out;

    const int GEMM_SMEM = 2 * STGB;   // 147456 (2 stages)
    cudaFuncSetAttribute(mma_gemm_kernel, cudaFuncAttributeMaxDynamicSharedMemorySize,
                         GEMM_SMEM);
    const int LOGITS_SMEM = (DIMV * LCN + 8 * 128) * sizeof(float);  // 55296 B
    cudaFuncSetAttribute(logits_kernel, cudaFuncAttributeMaxDynamicSharedMemorySize,
                         LOGITS_SMEM);

    zero_kernel<<<(N2 * NR + 255) / 256, 256>>>();
    hist_kernel<<<(EDGES + 255) / 256, 256>>>(ei1, ei2, et2);
    scan_p1<<<NPBLKS, 1024>>>();
    scan_p2<<<1, 64>>>();
    scan_p3<<<NPBLKS, 1024>>>();
    scatter_kernel<<<(EDGES + 255) / 256, 256>>>(ei1, ei2, et2);
    concept_kernel<<<N1 / 8, 256>>>((const float4*)x0);
    wbuild_kernel<<<(DIMV * KTOT + 255) / 256, 256>>>(root1, basis1, root2, basis2);

    agg_kernel<<<N2 / 8, 256>>>(0, comp1);
    mma_gemm_kernel<<<(N2 + 127) / 128, 256, GEMM_SMEM>>>(0, bias1, 1);
    agg_kernel<<<N2 / 8, 256>>>(1, comp2);
    mma_gemm_kernel<<<(N2 + 127) / 128, 256, GEMM_SMEM>>>(1, bias2, 0);

    tyw_kernel<<<(DIMV * LCN + 255) / 256, 256>>>(lc, w);
    logits_kernel<<<296, 256, LOGITS_SMEM>>>(out);
}

// round 5
// speedup vs baseline: 2.2133x; 1.1855x over previous
#include <cuda_runtime.h>
#include <cuda_bf16.h>
#include <cstdint>

#define N1 60000
#define N2 50000
#define EDGES 800000
#define DIMV 128
#define NR 16
#define LCN 100
#define KTOT 640
#define P1BLKS 59   // ceil(60000/1024)
#define P2BLKS 49   // ceil(50000/1024)
#define NPBLKS (P1BLKS + P2BLKS)

// ------------------------- scratch (device globals) -------------------------
__device__ float g_xg1[N2 * DIMV];                 // concept-layer output (relu'd), rows < N2
__device__ __nv_bfloat16 g_Ah[N2 * KTOT];          // [x | agg4] hi (bf16)
__device__ __nv_bfloat16 g_Al[N2 * KTOT];          // [x | agg4] lo (bf16)
__device__ float g_xa[N2 * DIMV];                  // rgcn1 output (relu'd)
__device__ __nv_bfloat16 g_xbh[N2 * DIMV];         // rgcn2 output hi
__device__ __nv_bfloat16 g_xbl[N2 * DIMV];         // rgcn2 output lo
__device__ __nv_bfloat16 g_Wh[2 * DIMV * KTOT];    // Wt[n][k] hi, both layers
__device__ __nv_bfloat16 g_Wl[2 * DIMV * KTOT];    // Wt[n][k] lo
__device__ __nv_bfloat16 g_Th[128 * DIMV];         // (ty*w) hi, rows 100..127 zero
__device__ __nv_bfloat16 g_Tl[128 * DIMV];         // (ty*w) lo
__device__ int g_hist1[N1];
__device__ int g_rp1[N1 + 1];
__device__ int g_cur1[N1];
__device__ int g_col1[EDGES];
__device__ int g_hist2[N2];
__device__ int g_rp2[N2 + 1];
__device__ int g_cur2[N2];
__device__ int g_col2[EDGES];                      // packed: src | (etype<<16)
__device__ int g_cseg[N2 * NR];
__device__ int g_part[NPBLKS];
__device__ int g_partsum[NPBLKS];

// ------------------------------- CSR build ----------------------------------
__global__ void zero_kernel() {
    int i = blockIdx.x * blockDim.x + threadIdx.x;
    if (i < N1) g_hist1[i] = 0;
    if (i < N2) g_hist2[i] = 0;
    if (i < N2 * NR) g_cseg[i] = 0;
}

__global__ void hist_kernel(const int* __restrict__ ei1,
                            const int* __restrict__ ei2,
                            const int* __restrict__ et2) {
    int i = blockIdx.x * blockDim.x + threadIdx.x;
    if (i >= EDGES) return;
    atomicAdd(&g_hist1[ei1[EDGES + i]], 1);
    int d2 = ei2[EDGES + i];
    atomicAdd(&g_hist2[d2], 1);
    atomicAdd(&g_cseg[d2 * NR + et2[i]], 1);
}

// ---- 3-phase scan: block-local scan -> partials scan -> add offsets --------
__global__ void scan_p1() {
    int b = blockIdx.x;
    const int* arr;
    int n, base;
    int* rp;
    if (b < P1BLKS) { arr = g_hist1; n = N1; base = b << 10; rp = g_rp1; }
    else { arr = g_hist2; n = N2; base = (b - P1BLKS) << 10; rp = g_rp2; }
    int tid = threadIdx.x, lane = tid & 31, wid = tid >> 5;
    __shared__ int wsum[32];
    int i = base + tid;
    int v = (i < n) ? arr[i] : 0;
    int inc = v;
    #pragma unroll
    for (int off = 1; off < 32; off <<= 1) {
        int t = __shfl_up_sync(0xFFFFFFFFu, inc, off);
        if (lane >= off) inc += t;
    }
    if (lane == 31) wsum[wid] = inc;
    __syncthreads();
    if (wid == 0) {
        int s = wsum[lane];
        #pragma unroll
        for (int off = 1; off < 32; off <<= 1) {
            int t = __shfl_up_sync(0xFFFFFFFFu, s, off);
            if (lane >= off) s += t;
        }
        wsum[lane] = s;
    }
    __syncthreads();
    int woff = wid ? wsum[wid - 1] : 0;
    if (i < n) rp[i] = woff + inc - v;
    if (tid == 1023) g_part[b] = woff + inc;
}

__global__ void scan_p2() {
    int tid = threadIdx.x, lane = tid & 31, wid = tid >> 5;
    int off = wid ? P1BLKS : 0;
    int cnt = wid ? P2BLKS : P1BLKS;
    int carry = 0;
    for (int base = 0; base < cnt; base += 32) {
        int k = base + lane;
        int v = (k < cnt) ? g_part[off + k] : 0;
        int inc = v;
        #pragma unroll
        for (int o = 1; o < 32; o <<= 1) {
            int t = __shfl_up_sync(0xFFFFFFFFu, inc, o);
            if (lane >= o) inc += t;
        }
        if (k < cnt) g_partsum[off + k] = carry + inc - v;
        carry += __shfl_sync(0xFFFFFFFFu, inc, 31);
    }
    if (lane == 0) {
        if (wid == 0) g_rp1[N1] = carry;
        else g_rp2[N2] = carry;
    }
}

__global__ void scan_p3() {
    int b = blockIdx.x;
    int n, base;
    int *rp, *cur;
    if (b < P1BLKS) { n = N1; base = b << 10; rp = g_rp1; cur = g_cur1; }
    else { n = N2; base = (b - P1BLKS) << 10; rp = g_rp2; cur = g_cur2; }
    int i = base + threadIdx.x;
    if (i < n) {
        int v = rp[i] + g_partsum[b];
        rp[i] = v;
        cur[i] = v;
    }
}

__global__ void scatter_kernel(const int* __restrict__ ei1,
                               const int* __restrict__ ei2,
                               const int* __restrict__ et2) {
    int i = blockIdx.x * blockDim.x + threadIdx.x;
    if (i >= EDGES) return;
    int s1 = ei1[i], d1 = ei1[EDGES + i];
    g_col1[atomicAdd(&g_cur1[d1], 1)] = s1;
    int s2 = ei2[i], d2 = ei2[EDGES + i], t = et2[i];
    g_col2[atomicAdd(&g_cur2[d2], 1)] = s2 | (t << 16);
}

// ------------------------------- concept ------------------------------------
// only rows < N2 are materialized (rows >= N2 feed only ty, computed separately)
__global__ void concept_kernel(const float4* __restrict__ x) {
    int gw = (blockIdx.x * blockDim.x + threadIdx.x) >> 5;
    if (gw >= N2) return;
    int lane = threadIdx.x & 31;
    int b = g_rp1[gw], e = g_rp1[gw + 1];
    float4 acc = make_float4(0.f, 0.f, 0.f, 0.f);
    float4 acc2 = acc;
    int j = b;
    for (; j + 2 <= e; j += 2) {
        int s0 = g_col1[j], s1 = g_col1[j + 1];
        float4 x0 = x[s0 * 32 + lane];
        float4 x1 = x[s1 * 32 + lane];
        acc.x += x0.x; acc.y += x0.y; acc.z += x0.z; acc.w += x0.w;
        acc2.x += x1.x; acc2.y += x1.y; acc2.z += x1.z; acc2.w += x1.w;
    }
    if (j < e) {
        float4 x0 = x[g_col1[j] * 32 + lane];
        acc.x += x0.x; acc.y += x0.y; acc.z += x0.z; acc.w += x0.w;
    }
    acc.x += acc2.x; acc.y += acc2.y; acc.z += acc2.z; acc.w += acc2.w;
    float inv = 1.f / (float)max(e - b, 1);
    float4 xv = x[gw * 32 + lane];
    float4 r;
    r.x = fmaxf(fmaf(acc.x, inv, xv.x), 0.f);
    r.y = fmaxf(fmaf(acc.y, inv, xv.y), 0.f);
    r.z = fmaxf(fmaf(acc.z, inv, xv.z), 0.f);
    r.w = fmaxf(fmaf(acc.w, inv, xv.w), 0.f);
    ((float4*)g_xg1)[gw * 32 + lane] = r;
}

// --------------------------- bf16 split helpers ------------------------------
__device__ __forceinline__ void bsplit(float v, __nv_bfloat16& h, __nv_bfloat16& l) {
    h = __float2bfloat16(v);
    l = __float2bfloat16(v - __bfloat162float(h));
}

__device__ __forceinline__ uint32_t pack2h(float a, float b) {
    __nv_bfloat16 ha, la, hb, lb;
    bsplit(a, ha, la); bsplit(b, hb, lb);
    return (uint32_t)__bfloat16_as_ushort(ha) | ((uint32_t)__bfloat16_as_ushort(hb) << 16);
}
__device__ __forceinline__ uint32_t pack2l(float a, float b) {
    __nv_bfloat16 ha, la, hb, lb;
    bsplit(a, ha, la); bsplit(b, hb, lb);
    return (uint32_t)__bfloat16_as_ushort(la) | ((uint32_t)__bfloat16_as_ushort(lb) << 16);
}

// ------------------------- ty rows: concept(lc) * w --------------------------
__global__ void ty_kernel(const float4* __restrict__ x, const int* __restrict__ lc,
                          const float4* __restrict__ w4) {
    int gw = (blockIdx.x * blockDim.x + threadIdx.x) >> 5;
    if (gw >= 128) return;
    int lane = threadIdx.x & 31;
    uint2 H = make_uint2(0, 0), L = make_uint2(0, 0);
    if (gw < LCN) {
        int v = lc[gw];
        int b = g_rp1[v], e = g_rp1[v + 1];
        float4 acc = make_float4(0.f, 0.f, 0.f, 0.f);
        for (int j = b; j < e; j++) {
            float4 xs = x[g_col1[j] * 32 + lane];
            acc.x += xs.x; acc.y += xs.y; acc.z += xs.z; acc.w += xs.w;
        }
        float inv = 1.f / (float)max(e - b, 1);
        float4 xv = x[v * 32 + lane];
        float4 wv = w4[lane];
        float4 r;
        r.x = fmaxf(fmaf(acc.x, inv, xv.x), 0.f) * wv.x;
        r.y = fmaxf(fmaf(acc.y, inv, xv.y), 0.f) * wv.y;
        r.z = fmaxf(fmaf(acc.z, inv, xv.z), 0.f) * wv.z;
        r.w = fmaxf(fmaf(acc.w, inv, xv.w), 0.f) * wv.w;
        H.x = pack2h(r.x, r.y); H.y = pack2h(r.z, r.w);
        L.x = pack2l(r.x, r.y); L.y = pack2l(r.z, r.w);
    }
    *(uint2*)(g_Th + gw * DIMV + lane * 4) = H;
    *(uint2*)(g_Tl + gw * DIMV + lane * 4) = L;
}

// --------------------------- weights (bf16 split, transposed) ---------------
__global__ void wbuild_kernel(const float* __restrict__ root1, const float* __restrict__ b1,
                              const float* __restrict__ root2, const float* __restrict__ b2) {
    int i = blockIdx.x * blockDim.x + threadIdx.x;
    if (i >= DIMV * KTOT) return;
    int n = i / KTOT, k = i % KTOT;
    float v1 = (k < 128) ? root1[k * 128 + n] : b1[(k - 128) * 128 + n];
    float v2 = (k < 128) ? root2[k * 128 + n] : b2[(k - 128) * 128 + n];
    bsplit(v1, g_Wh[i], g_Wl[i]);
    bsplit(v2, g_Wh[DIMV * KTOT + i], g_Wl[DIMV * KTOT + i]);
}

// --------------------------- RGCN aggregation -------------------------------
__device__ __forceinline__ void split_store4(float4 v, size_t off) {
    uint2 H, L;
    H.x = pack2h(v.x, v.y); H.y = pack2h(v.z, v.w);
    L.x = pack2l(v.x, v.y); L.y = pack2l(v.z, v.w);
    *(uint2*)(g_Ah + off) = H;
    *(uint2*)(g_Al + off) = L;
}

__device__ __forceinline__ void agg_fma(float4& a0, float4& a1, float4& a2, float4& a3,
                                        float4 c4, float nz, float4 xs) {
    float c0 = c4.x * nz, c1 = c4.y * nz, c2 = c4.z * nz, c3 = c4.w * nz;
    a0.x = fmaf(c0, xs.x, a0.x); a0.y = fmaf(c0, xs.y, a0.y);
    a0.z = fmaf(c0, xs.z, a0.z); a0.w = fmaf(c0, xs.w, a0.w);
    a1.x = fmaf(c1, xs.x, a1.x); a1.y = fmaf(c1, xs.y, a1.y);
    a1.z = fmaf(c1, xs.z, a1.z); a1.w = fmaf(c1, xs.w, a1.w);
    a2.x = fmaf(c2, xs.x, a2.x); a2.y = fmaf(c2, xs.y, a2.y);
    a2.z = fmaf(c2, xs.z, a2.z); a2.w = fmaf(c2, xs.w, a2.w);
    a3.x = fmaf(c3, xs.x, a3.x); a3.y = fmaf(c3, xs.y, a3.y);
    a3.z = fmaf(c3, xs.z, a3.z); a3.w = fmaf(c3, xs.w, a3.w);
}

__global__ void agg_kernel(int layer, const float* __restrict__ comp) {
    __shared__ float4 comps[NR];
    int tid = threadIdx.x;
    if (tid < NR)
        comps[tid] = make_float4(comp[tid * 4 + 0], comp[tid * 4 + 1],
                                 comp[tid * 4 + 2], comp[tid * 4 + 3]);
    __syncthreads();
    int gw = (blockIdx.x * blockDim.x + tid) >> 5;
    if (gw >= N2) return;
    int lane = tid & 31;
    const float4* x = layer ? (const float4*)g_xa : (const float4*)g_xg1;

    float nrm = 0.f;
    if (lane < NR) nrm = 1.f / (float)max(g_cseg[gw * NR + lane], 1);

    int b = g_rp2[gw], e = g_rp2[gw + 1];
    float4 a0 = make_float4(0.f, 0.f, 0.f, 0.f);
    float4 a1 = a0, a2 = a0, a3 = a0;
    int j = b;
    for (; j + 4 <= e; j += 4) {
        int pk0 = g_col2[j], pk1 = g_col2[j + 1];
        int pk2 = g_col2[j + 2], pk3 = g_col2[j + 3];
        int s0 = pk0 & 0xFFFF, t0 = pk0 >> 16;
        int s1 = pk1 & 0xFFFF, t1 = pk1 >> 16;
        int s2 = pk2 & 0xFFFF, t2 = pk2 >> 16;
        int s3 = pk3 & 0xFFFF, t3 = pk3 >> 16;
        float4 x0 = x[s0 * 32 + lane];
        float4 x1 = x[s1 * 32 + lane];
        float4 x2 = x[s2 * 32 + lane];
        float4 x3 = x[s3 * 32 + lane];
        float nz0 = __shfl_sync(0xFFFFFFFFu, nrm, t0);
        float nz1 = __shfl_sync(0xFFFFFFFFu, nrm, t1);
        float nz2 = __shfl_sync(0xFFFFFFFFu, nrm, t2);
        float nz3 = __shfl_sync(0xFFFFFFFFu, nrm, t3);
        agg_fma(a0, a1, a2, a3, comps[t0], nz0, x0);
        agg_fma(a0, a1, a2, a3, comps[t1], nz1, x1);
        agg_fma(a0, a1, a2, a3, comps[t2], nz2, x2);
        agg_fma(a0, a1, a2, a3, comps[t3], nz3, x3);
    }
    for (; j < e; j++) {
        int pk = g_col2[j];
        int s = pk & 0xFFFF, t = pk >> 16;
        float nz = __shfl_sync(0xFFFFFFFFu, nrm, t);
        agg_fma(a0, a1, a2, a3, comps[t], nz, x[s * 32 + lane]);
    }
    size_t base = (size_t)gw * KTOT + lane * 4;
    split_store4(x[gw * 32 + lane], base);
    split_store4(a0, base + 128);
    split_store4(a1, base + 256);
    split_store4(a2, base + 384);
    split_store4(a3, base + 512);
}

// --------------------------- HMMA split-bf16 GEMM ---------------------------
#define KC 64
#define SROW 72
#define SROW4 9
#define SBUF (128 * SROW)
#define STGB (4 * SBUF * 2)
#define BUFB (SBUF * 2)

__device__ __forceinline__ void mma_bf16(float* c, const uint32_t* a, const uint32_t* b) {
    asm volatile(
        "mma.sync.aligned.m16n8k16.row.col.f32.bf16.bf16.f32 "
        "{%0,%1,%2,%3}, {%4,%5,%6,%7}, {%8,%9}, {%0,%1,%2,%3};"
        : "+f"(c[0]), "+f"(c[1]), "+f"(c[2]), "+f"(c[3])
        : "r"(a[0]), "r"(a[1]), "r"(a[2]), "r"(a[3]), "r"(b[0]), "r"(b[1]));
}

__device__ __forceinline__ void cp16(uint32_t saddr, const void* g, bool pred) {
    int sz = pred ? 16 : 0;
    asm volatile("cp.async.cg.shared.global [%0], [%1], 16, %2;"
                 :: "r"(saddr), "l"(g), "r"(sz));
}

__global__ __launch_bounds__(256, 1) void mma_gemm_kernel(int layer,
                                                          const float* __restrict__ bias,
                                                          int relu) {
    extern __shared__ __nv_bfloat16 sm[];

    const int tid = threadIdx.x;
    const int wid = tid >> 5, lane = tid & 31;
    const int m0 = blockIdx.x * 128;
    const int m0w = (wid >> 2) * 64;
    const int n0w = (wid & 3) * 32;
    const int r = lane >> 2, q = lane & 3;

    const uint4* pAH = (const uint4*)g_Ah;
    const uint4* pAL = (const uint4*)g_Al;
    const uint4* pWH = (const uint4*)(g_Wh + (size_t)layer * DIMV * KTOT);
    const uint4* pWL = (const uint4*)(g_Wl + (size_t)layer * DIMV * KTOT);

    uint32_t sbase = (uint32_t)__cvta_generic_to_shared(sm);

    float acc[4][4][4];
    #pragma unroll
    for (int i = 0; i < 4; i++)
        #pragma unroll
        for (int j = 0; j < 4; j++)
            #pragma unroll
            for (int k = 0; k < 4; k++) acc[i][j][k] = 0.f;

    auto stage_load = [&](int c, int s) {
        const int kb = c * 8;
        uint32_t st = sbase + (uint32_t)s * STGB;
        #pragma unroll
        for (int j = 0; j < 4; j++) {
            int idx = tid + j * 256;
            int row = idx >> 3, col = idx & 7;
            uint32_t so = (uint32_t)(row * SROW4 + col) * 16;
            int m = m0 + row;
            bool ok = m < N2;
            size_t ga = (size_t)(ok ? m : 0) * 80 + kb + col;
            cp16(st + so, pAH + ga, ok);
            cp16(st + BUFB + so, pAL + ga, ok);
            size_t wo = (size_t)row * 80 + kb + col;
            cp16(st + 2 * BUFB + so, pWH + wo, true);
            cp16(st + 3 * BUFB + so, pWL + wo, true);
        }
        asm volatile("cp.async.commit_group;");
    };

    stage_load(0, 0);
    for (int c = 0; c < KTOT / KC; c++) {
        if (c < KTOT / KC - 1) {
            stage_load(c + 1, (c + 1) & 1);
            asm volatile("cp.async.wait_group 1;");
        } else {
            asm volatile("cp.async.wait_group 0;");
        }
        __syncthreads();

        const __nv_bfloat16* sbuf = sm + (size_t)(c & 1) * (4 * SBUF);
        const uint32_t* Ah32 = (const uint32_t*)sbuf;
        const uint32_t* Al32 = (const uint32_t*)(sbuf + SBUF);
        const uint32_t* Bh32 = (const uint32_t*)(sbuf + 2 * SBUF);
        const uint32_t* Bl32 = (const uint32_t*)(sbuf + 3 * SBUF);

        #pragma unroll
        for (int kk = 0; kk < KC; kk += 16) {
            const int kw = kk >> 1;
            uint32_t ah[4][4], al[4][4], bh[4][2], bl[4][2];
            #pragma unroll
            for (int mt = 0; mt < 4; mt++) {
                int row0 = (m0w + mt * 16 + r) * (SROW / 2);
                int row8 = row0 + 8 * (SROW / 2);
                ah[mt][0] = Ah32[row0 + kw + q];
                ah[mt][1] = Ah32[row8 + kw + q];
                ah[mt][2] = Ah32[row0 + kw + 4 + q];
                ah[mt][3] = Ah32[row8 + kw + 4 + q];
                al[mt][0] = Al32[row0 + kw + q];
                al[mt][1] = Al32[row8 + kw + q];
                al[mt][2] = Al32[row0 + kw + 4 + q];
                al[mt][3] = Al32[row8 + kw + 4 + q];
            }
            #pragma unroll
            for (int nt = 0; nt < 4; nt++) {
                int nrow = (n0w + nt * 8 + r) * (SROW / 2);
                bh[nt][0] = Bh32[nrow + kw + q];
                bh[nt][1] = Bh32[nrow + kw + 4 + q];
                bl[nt][0] = Bl32[nrow + kw + q];
                bl[nt][1] = Bl32[nrow + kw + 4 + q];
            }
            #pragma unroll
            for (int mt = 0; mt < 4; mt++)
                #pragma unroll
                for (int nt = 0; nt < 4; nt++) {
                    mma_bf16(acc[mt][nt], ah[mt], bh[nt]);
                    mma_bf16(acc[mt][nt], ah[mt], bl[nt]);
                    mma_bf16(acc[mt][nt], al[mt], bh[nt]);
                }
        }
        __syncthreads();
    }

    // epilogue: layer 0 -> fp32+relu into g_xa; layer 1 -> bf16 hi/lo split
    #pragma unroll
    for (int nt = 0; nt < 4; nt++) {
        int col = n0w + nt * 8 + q * 2;
        float b0 = bias[col], b1 = bias[col + 1];
        #pragma unroll
        for (int mt = 0; mt < 4; mt++) {
            int row = m0 + m0w + mt * 16 + r;
            float v00 = acc[mt][nt][0] + b0, v01 = acc[mt][nt][1] + b1;
            float v10 = acc[mt][nt][2] + b0, v11 = acc[mt][nt][3] + b1;
            if (relu) {
                v00 = fmaxf(v00, 0.f); v01 = fmaxf(v01, 0.f);
                v10 = fmaxf(v10, 0.f); v11 = fmaxf(v11, 0.f);
            }
            if (layer == 0) {
                if (row < N2)
                    *(float2*)(g_xa + (size_t)row * DIMV + col) = make_float2(v00, v01);
                if (row + 8 < N2)
                    *(float2*)(g_xa + (size_t)(row + 8) * DIMV + col) = make_float2(v10, v11);
            } else {
                if (row < N2) {
                    *(uint32_t*)(g_xbh + (size_t)row * DIMV + col) = pack2h(v00, v01);
                    *(uint32_t*)(g_xbl + (size_t)row * DIMV + col) = pack2l(v00, v01);
                }
                if (row + 8 < N2) {
                    *(uint32_t*)(g_xbh + (size_t)(row + 8) * DIMV + col) = pack2h(v10, v11);
                    *(uint32_t*)(g_xbl + (size_t)(row + 8) * DIMV + col) = pack2l(v10, v11);
                }
            }
        }
    }
}

// ---------------- logits: HMMA split-bf16 GEMM + fused softmax ---------------
#define SROWL 136          // smem row stride in bf16 for K=128 tiles
#define SROWL4 17
#define LBUF (128 * SROWL) // bf16 elems per buffer (17408)
#define LBUFB (LBUF * 2)   // bytes per buffer (34816)

__global__ __launch_bounds__(256, 1) void logits_kernel(float* __restrict__ out) {
    extern __shared__ __nv_bfloat16 sm[];

    const int tid = threadIdx.x;
    const int wid = tid >> 5, lane = tid & 31;
    const int m0 = blockIdx.x * 128;
    const int m0w = (wid >> 2) * 64;
    const int n0w = (wid & 3) * 32;
    const int r = lane >> 2, q = lane & 3;

    uint32_t sbase = (uint32_t)__cvta_generic_to_shared(sm);

    // stage A hi/lo (x_g2 rows) and B hi/lo (ty*w rows, 128 padded)
    const uint4* pAH = (const uint4*)g_xbh;   // 16 uint4 per row
    const uint4* pAL = (const uint4*)g_xbl;
    const uint4* pTH = (const uint4*)g_Th;
    const uint4* pTL = (const uint4*)g_Tl;
    #pragma unroll
    for (int j = 0; j < 8; j++) {
        int idx = tid + j * 256;
        int row = idx >> 4, col = idx & 15;
        uint32_t so = (uint32_t)(row * SROWL4 + col) * 16;
        int m = m0 + row;
        bool ok = m < N2;
        size_t ga = (size_t)(ok ? m : 0) * 16 + col;
        cp16(sbase + so, pAH + ga, ok);
        cp16(sbase + LBUFB + so, pAL + ga, ok);
        size_t ta = (size_t)row * 16 + col;
        cp16(sbase + 2 * LBUFB + so, pTH + ta, true);
        cp16(sbase + 3 * LBUFB + so, pTL + ta, true);
    }
    asm volatile("cp.async.commit_group;");
    asm volatile("cp.async.wait_group 0;");
    __syncthreads();

    float acc[4][4][4];
    #pragma unroll
    for (int i = 0; i < 4; i++)
        #pragma unroll
        for (int j = 0; j < 4; j++)
            #pragma unroll
            for (int k = 0; k < 4; k++) acc[i][j][k] = 0.f;

    const uint32_t* Ah32 = (const uint32_t*)sm;
    const uint32_t* Al32 = (const uint32_t*)(sm + LBUF);
    const uint32_t* Bh32 = (const uint32_t*)(sm + 2 * LBUF);
    const uint32_t* Bl32 = (const uint32_t*)(sm + 3 * LBUF);

    #pragma unroll
    for (int kk = 0; kk < 128; kk += 16) {
        const int kw = kk >> 1;
        uint32_t ah[4][4], al[4][4], bh[4][2], bl[4][2];
        #pragma unroll
        for (int mt = 0; mt < 4; mt++) {
            int row0 = (m0w + mt * 16 + r) * (SROWL / 2);
            int row8 = row0 + 8 * (SROWL / 2);
            ah[mt][0] = Ah32[row0 + kw + q];
            ah[mt][1] = Ah32[row8 + kw + q];
            ah[mt][2] = Ah32[row0 + kw + 4 + q];
            ah[mt][3] = Ah32[row8 + kw + 4 + q];
            al[mt][0] = Al32[row0 + kw + q];
            al[mt][1] = Al32[row8 + kw + q];
            al[mt][2] = Al32[row0 + kw + 4 + q];
            al[mt][3] = Al32[row8 + kw + 4 + q];
        }
        #pragma unroll
        for (int nt = 0; nt < 4; nt++) {
            int nrow = (n0w + nt * 8 + r) * (SROWL / 2);
            bh[nt][0] = Bh32[nrow + kw + q];
            bh[nt][1] = Bh32[nrow + kw + 4 + q];
            bl[nt][0] = Bl32[nrow + kw + q];
            bl[nt][1] = Bl32[nrow + kw + 4 + q];
        }
        #pragma unroll
        for (int mt = 0; mt < 4; mt++)
            #pragma unroll
            for (int nt = 0; nt < 4; nt++) {
                mma_bf16(acc[mt][nt], ah[mt], bh[nt]);
                mma_bf16(acc[mt][nt], ah[mt], bl[nt]);
                mma_bf16(acc[mt][nt], al[mt], bh[nt]);
            }
    }
    __syncthreads();

    // dump logits to smem (reuse staging region), stride 104 floats
    float* LS = (float*)sm;
    #pragma unroll
    for (int nt = 0; nt < 4; nt++) {
        int col = n0w + nt * 8 + q * 2;
        if (col < LCN) {
            #pragma unroll
            for (int mt = 0; mt < 4; mt++) {
                int row = m0w + mt * 16 + r;
                LS[row * 104 + col] = acc[mt][nt][0];
                LS[row * 104 + col + 1] = acc[mt][nt][1];
                LS[(row + 8) * 104 + col] = acc[mt][nt][2];
                LS[(row + 8) * 104 + col + 1] = acc[mt][nt][3];
            }
        }
    }
    __syncthreads();

    // softmax: each warp handles 16 rows
    #pragma unroll 1
    for (int i = 0; i < 16; i++) {
        int row = wid * 16 + i;
        int grow = m0 + row;
        float d0 = LS[row * 104 + lane];
        float d1 = LS[row * 104 + lane + 32];
        float d2 = LS[row * 104 + lane + 64];
        float d3 = (lane < 4) ? LS[row * 104 + lane + 96] : -1e30f;
        float mx = fmaxf(fmaxf(d0, d1), fmaxf(d2, d3));
        #pragma unroll
        for (int off = 16; off > 0; off >>= 1)
            mx = fmaxf(mx, __shfl_xor_sync(0xFFFFFFFFu, mx, off));
        float e0 = expf(d0 - mx), e1 = expf(d1 - mx), e2 = expf(d2 - mx);
        float e3 = (lane < 4) ? expf(d3 - mx) : 0.f;
        float s = e0 + e1 + e2 + e3;
        #pragma unroll
        for (int off = 16; off > 0; off >>= 1)
            s += __shfl_xor_sync(0xFFFFFFFFu, s, off);
        float inv = 1.f / s;
        if (grow < N2) {
            float* orow = out + (size_t)grow * LCN;
            orow[lane] = e0 * inv;
            orow[lane + 32] = e1 * inv;
            orow[lane + 64] = e2 * inv;
            if (lane < 4) orow[lane + 96] = e3 * inv;
        }
    }
}

// ------------------------------- launcher -----------------------------------
extern "C" void kernel_launch(void* const* d_in, const int* in_sizes, int n_in,
                              void* d_out, int out_size) {
    const int* ei2 = (const int*)d_in[0];
    const int* et2 = (const int*)d_in[1];
    const int* ei1 = (const int*)d_in[2];
    const int* lc  = (const int*)d_in[3];
    const float* x0     = (const float*)d_in[4];
    const float* basis1 = (const float*)d_in[5];
    const float* comp1  = (const float*)d_in[6];
    const float* root1  = (const float*)d_in[7];
    const float* bias1  = (const float*)d_in[8];
    const float* basis2 = (const float*)d_in[9];
    const float* comp2  = (const float*)d_in[10];
    const float* root2  = (const float*)d_in[11];
    const float* bias2  = (const float*)d_in[12];
    const float* w      = (const float*)d_in[13];
    float* out = (float*)d_out;

    const int GEMM_SMEM = 2 * STGB;            // 147456
    cudaFuncSetAttribute(mma_gemm_kernel, cudaFuncAttributeMaxDynamicSharedMemorySize,
                         GEMM_SMEM);
    const int LOGITS_SMEM = 4 * LBUFB;         // 139264
    cudaFuncSetAttribute(logits_kernel, cudaFuncAttributeMaxDynamicSharedMemorySize,
                         LOGITS_SMEM);

    zero_kernel<<<(N2 * NR + 255) / 256, 256>>>();
    hist_kernel<<<(EDGES + 255) / 256, 256>>>(ei1, ei2, et2);
    scan_p1<<<NPBLKS, 1024>>>();
    scan_p2<<<1, 64>>>();
    scan_p3<<<NPBLKS, 1024>>>();
    scatter_kernel<<<(EDGES + 255) / 256, 256>>>(ei1, ei2, et2);
    concept_kernel<<<N2 / 8, 256>>>((const float4*)x0);
    ty_kernel<<<16, 256>>>((const float4*)x0, lc, (const float4*)w);
    wbuild_kernel<<<(DIMV * KTOT + 255) / 256, 256>>>(root1, basis1, root2, basis2);

    agg_kernel<<<N2 / 8, 256>>>(0, comp1);
    mma_gemm_kernel<<<(N2 + 127) / 128, 256, GEMM_SMEM>>>(0, bias1, 1);
    agg_kernel<<<N2 / 8, 256>>>(1, comp2);
    mma_gemm_kernel<<<(N2 + 127) / 128, 256, GEMM_SMEM>>>(1, bias2, 0);

    logits_kernel<<<(N2 + 127) / 128, 256, LOGITS_SMEM>>>(out);
}